// round 1
// baseline (speedup 1.0000x reference)
#include <cuda_runtime.h>

#define GH 52
#define GW 52
#define NB 5
#define NBOX (GH*GW*NB)          // 13520
#define MAXPRED 44
#define IOU_T 0.4f

// Scratch (allocation-free: __device__ globals)
__device__ float4 g_box[NBOX];
__device__ float  g_score[NBOX];
__device__ int    g_pred[NBOX][MAXPRED];
__device__ int    g_pcnt[NBOX];

// ---------------------------------------------------------------------------
// Kernel 1: decode boxes. One thread per box.
// Input layout: x[1, 52, 52, 25] contiguous; box n = cell*5 + b reads
// x[cell*25 + b*5 + {0..4}].
// ---------------------------------------------------------------------------
__global__ void decode_kernel(const float* __restrict__ x, float* __restrict__ out)
{
    int n = blockIdx.x * blockDim.x + threadIdx.x;
    if (n >= NBOX) return;
    int cell = n / NB;
    int b    = n - cell * NB;
    int gy   = cell / GW;
    int gx   = cell - gy * GW;

    const float* p = x + cell * (NB * 5) + b * 5;
    float c0 = p[0], c1 = p[1], c2 = p[2], c3 = p[3], s = p[4];

    const float sx = 416.0f / GW;   // 8
    const float sy = 416.0f / GH;   // 8
    float cx = (c0 + (float)gx) * sx;
    float w  = c2 * sx;
    float cy = (c1 + (float)gy) * sy;
    float h  = c3 * sy;
    cy = 416.0f - cy;

    float x1 = cx - w * 0.5f;
    float y1 = cy - h * 0.5f;
    float x2 = cx + w * 0.5f;
    float y2 = cy + h * 0.5f;

    g_box[n]   = make_float4(x1, y1, x2, y2);
    g_score[n] = s;

    float* o = out + n * 5;
    o[0] = x1; o[1] = y1; o[2] = x2; o[3] = y2;
    // o[4] (nms score) written by nms_kernel.
}

// ---------------------------------------------------------------------------
// Kernel 2: build predecessor lists. One thread per box.
// Boxes are < 8px wide/tall and cell pitch is 8px, so IoU > 0 is only
// possible within the ±1 cell neighborhood (45 boxes incl. self).
// pred(i -> j) iff i has higher priority (score desc, index asc tiebreak,
// matching stable argsort(-scores)) and IoU(i,j) > 0.4.
// ---------------------------------------------------------------------------
__global__ void edges_kernel()
{
    int j = blockIdx.x * blockDim.x + threadIdx.x;
    if (j >= NBOX) return;
    int cell = j / NB;
    int gy   = cell / GW;
    int gx   = cell - gy * GW;

    float4 bj = g_box[j];
    float  sj = g_score[j];
    float  aj = fmaxf(bj.z - bj.x, 0.0f) * fmaxf(bj.w - bj.y, 0.0f);

    int cnt = 0;
    #pragma unroll
    for (int dy = -1; dy <= 1; dy++) {
        int ny = gy + dy;
        if (ny < 0 || ny >= GH) continue;
        #pragma unroll
        for (int dx = -1; dx <= 1; dx++) {
            int nx = gx + dx;
            if (nx < 0 || nx >= GW) continue;
            int base = (ny * GW + nx) * NB;
            #pragma unroll
            for (int bb = 0; bb < NB; bb++) {
                int i = base + bb;
                if (i == j) continue;
                float si = g_score[i];
                bool higher = (si > sj) || (si == sj && i < j);
                if (!higher) continue;
                float4 bi = g_box[i];
                float iw = fminf(bi.z, bj.z) - fmaxf(bi.x, bj.x);
                float ih = fminf(bi.w, bj.w) - fmaxf(bi.y, bj.y);
                iw = fmaxf(iw, 0.0f);
                ih = fmaxf(ih, 0.0f);
                float inter = iw * ih;
                float ai  = fmaxf(bi.z - bi.x, 0.0f) * fmaxf(bi.w - bi.y, 0.0f);
                float uni = ai + aj - inter;
                float iou = (uni > 0.0f) ? inter / fmaxf(uni, 1e-12f) : 0.0f;
                if (iou > IOU_T)
                    g_pred[j][cnt++] = i;
            }
        }
    }
    g_pcnt[j] = cnt;
}

// ---------------------------------------------------------------------------
// Kernel 3: Jacobi fixpoint NMS (single block) + score writeout.
// kept[j] = NOT any(kept[pred]). Unique fixpoint == greedy NMS result.
// Early exit when a sweep changes nothing (deterministic per input,
// graph-capturable: pure device-side loop).
// ---------------------------------------------------------------------------
#define NMS_THREADS 1024

__global__ void nms_kernel(float* __restrict__ out)
{
    __shared__ unsigned char kept[2][NBOX];   // 2 * 13520 B
    __shared__ int changed;

    int t = threadIdx.x;
    for (int j = t; j < NBOX; j += NMS_THREADS)
        kept[0][j] = 1;

    int cur = 0;
    for (int it = 0; it < NBOX; it++) {
        if (t == 0) changed = 0;
        __syncthreads();   // init/reset visible; prior sweep's kept visible

        int nxt = cur ^ 1;
        int ch  = 0;
        for (int j = t; j < NBOX; j += NMS_THREADS) {
            int c = g_pcnt[j];
            const int* pr = g_pred[j];
            unsigned char any = 0;
            for (int k = 0; k < c; k++)
                any |= kept[cur][pr[k]];
            unsigned char v = (unsigned char)(!any);
            kept[nxt][j] = v;
            ch |= (v != kept[cur][j]);
        }
        if (ch) changed = 1;          // benign race: all writers store 1
        __syncthreads();              // all writes to changed done
        int done = !changed;
        __syncthreads();              // all reads of changed done before reset
        cur = nxt;
        if (done) break;
    }

    for (int j = t; j < NBOX; j += NMS_THREADS)
        out[j * 5 + 4] = kept[cur][j] ? g_score[j] : 0.0f;
}

// ---------------------------------------------------------------------------
extern "C" void kernel_launch(void* const* d_in, const int* in_sizes, int n_in,
                              void* d_out, int out_size)
{
    const float* x   = (const float*)d_in[0];
    float*       out = (float*)d_out;

    const int threads = 256;
    const int blocks  = (NBOX + threads - 1) / threads;   // 53

    decode_kernel<<<blocks, threads>>>(x, out);
    edges_kernel<<<blocks, threads>>>();
    nms_kernel<<<1, NMS_THREADS>>>(out);
}

// round 2
// speedup vs baseline: 1.0950x; 1.0950x over previous
#include <cuda_runtime.h>
#include <stdint.h>

#define GH 52
#define GW 52
#define NB 5
#define NBOX (GH*GW*NB)            // 13520
#define WORDS ((NBOX + 31) / 32)   // 423
#define KWORDS 448                 // padded-up word count for kept bitmap body
#define KPAD 16                    // pad words each side of kept bitmap (512 bits)
#define IOU_T 0.4f

// Scratch (allocation-free)
__device__ unsigned long long g_pmask[NBOX];

// ---------------------------------------------------------------------------
// Kernel 1: decode + predecessor bitmask. One thread per box.
// Boxes are < 8px wide/tall, cell pitch is 8px -> IoU>0 only within the
// +/-1-cell neighborhood (45 boxes). pred bit layout:
//   bit = (dy+1)*15 + (dx+1)*5 + bb   (dy,dx in {-1,0,1}, bb in [0,5))
// pred(i -> j) iff priority(i) > priority(j) (score desc, index asc tiebreak,
// matching stable argsort(-scores)) and IoU(i,j) > 0.4.
// Neighbor boxes are re-decoded from x (identical fp32 op sequence -> exact).
// ---------------------------------------------------------------------------
__global__ void decode_edges_kernel(const float* __restrict__ x,
                                    float* __restrict__ out)
{
    int j = blockIdx.x * blockDim.x + threadIdx.x;
    if (j >= NBOX) return;
    int cell = j / NB;
    int b    = j - cell * NB;
    int gy   = cell / GW;
    int gx   = cell - gy * GW;

    const float sx = 416.0f / GW;   // 8
    const float sy = 416.0f / GH;   // 8

    const float* p = x + j * 5;     // j*5 == cell*25 + b*5
    float c0 = p[0], c1 = p[1], c2 = p[2], c3 = p[3], sj = p[4];

    float cx = (c0 + (float)gx) * sx;
    float w  = c2 * sx;
    float cy = (c1 + (float)gy) * sy;
    float h  = c3 * sy;
    cy = 416.0f - cy;
    float jx1 = cx - w * 0.5f, jy1 = cy - h * 0.5f;
    float jx2 = cx + w * 0.5f, jy2 = cy + h * 0.5f;

    float* o = out + j * 5;
    o[0] = jx1; o[1] = jy1; o[2] = jx2; o[3] = jy2;
    // o[4] written by nms_kernel.

    float aj = fmaxf(jx2 - jx1, 0.0f) * fmaxf(jy2 - jy1, 0.0f);

    unsigned long long mask = 0;
    #pragma unroll
    for (int dy = -1; dy <= 1; dy++) {
        int ny = gy + dy;
        if ((unsigned)ny >= GH) continue;
        #pragma unroll
        for (int dx = -1; dx <= 1; dx++) {
            int nx = gx + dx;
            if ((unsigned)nx >= GW) continue;
            int ncell = ny * GW + nx;
            #pragma unroll
            for (int bb = 0; bb < NB; bb++) {
                int i = ncell * NB + bb;
                if (i == j) continue;
                const float* q = x + i * 5;
                float si = q[4];
                bool higher = (si > sj) || (si == sj && i < j);
                if (!higher) continue;
                float d0 = q[0], d1 = q[1], d2 = q[2], d3 = q[3];
                float icx = (d0 + (float)nx) * sx;
                float iw_ = d2 * sx;
                float icy = (d1 + (float)ny) * sy;
                float ih_ = d3 * sy;
                icy = 416.0f - icy;
                float ix1 = icx - iw_ * 0.5f, iy1 = icy - ih_ * 0.5f;
                float ix2 = icx + iw_ * 0.5f, iy2 = icy + ih_ * 0.5f;

                float iw = fmaxf(fminf(ix2, jx2) - fmaxf(ix1, jx1), 0.0f);
                float ih = fmaxf(fminf(iy2, jy2) - fmaxf(iy1, jy1), 0.0f);
                float inter = iw * ih;
                float ai  = fmaxf(ix2 - ix1, 0.0f) * fmaxf(iy2 - iy1, 0.0f);
                float uni = ai + aj - inter;
                float iou = (uni > 0.0f) ? inter / fmaxf(uni, 1e-12f) : 0.0f;
                if (iou > IOU_T) {
                    int bit = (dy + 1) * 15 + (dx + 1) * 5 + bb;
                    mask |= 1ull << bit;
                }
            }
        }
    }
    g_pmask[j] = mask;
}

// ---------------------------------------------------------------------------
// Kernel 2: bitmask fixpoint NMS, single block, in-place Gauss-Seidel with
// dirty-window frontier. kept bitmap lives in shared memory. A word is
// recomputed only if a kept-word within +/-9 words changed last sweep.
// Converges to the unique fixpoint == exact greedy NMS; termination is a
// verified full-sweep no-change.
// ---------------------------------------------------------------------------
#define NMS_T 1024

__global__ void nms_kernel(const float* __restrict__ x, float* __restrict__ out)
{
    __shared__ uint32_t kept[KPAD + KWORDS + KPAD];   // 480 words
    __shared__ uint32_t dirty[2][18];                 // bit (w+32) of each map
    __shared__ int s_changed;

    int t    = threadIdx.x;
    int lane = t & 31;
    int wid  = t >> 5;

    // Init kept: boxes 0..13519 = 1, everything else (incl. padding) = 0.
    for (int i = t; i < KPAD + KWORDS + KPAD; i += NMS_T) {
        int w = i - KPAD;
        uint32_t v = 0;
        if (w >= 0 && w < WORDS - 1) v = 0xFFFFFFFFu;
        else if (w == WORDS - 1)     v = 0x0000FFFFu;  // boxes 13504..13519
        kept[i] = v;
    }
    if (t < 18) { dirty[0][t] = 0xFFFFFFFFu; dirty[1][t] = 0; }
    if (t == 0) s_changed = 0;
    __syncthreads();

    int cur = 0;
    for (int sweep = 0; sweep < NBOX; sweep++) {
        for (int w = wid; w < WORDS; w += 32) {
            // dirty window: bits [w-9, w+10] of dirty map (stored at +32)
            int bi = w + 23;
            uint64_t win = (uint64_t)dirty[cur][bi >> 5] |
                           ((uint64_t)dirty[cur][(bi >> 5) + 1] << 32);
            if (((win >> (bi & 31)) & 0xFFFFFu) == 0) continue;

            int  j     = w * 32 + lane;
            bool valid = j < NBOX;
            unsigned long long pm = valid ? __ldg(&g_pmask[j]) : 0ull;

            int b    = j - (j / 5) * 5;
            int base = j - b - 5 + KPAD * 32;   // bit pos of row dy=0 start

            int p0 = base - 260;
            uint64_t r;
            r = ((uint64_t)kept[p0 >> 5] | ((uint64_t)kept[(p0 >> 5) + 1] << 32))
                >> (p0 & 31);
            uint32_t rm1 = (uint32_t)r & 0x7FFFu;
            r = ((uint64_t)kept[base >> 5] | ((uint64_t)kept[(base >> 5) + 1] << 32))
                >> (base & 31);
            uint32_t r0 = (uint32_t)r & 0x7FFFu;
            int p2 = base + 260;
            r = ((uint64_t)kept[p2 >> 5] | ((uint64_t)kept[(p2 >> 5) + 1] << 32))
                >> (p2 & 31);
            uint32_t rp1 = (uint32_t)r & 0x7FFFu;

            uint64_t nb = (uint64_t)rm1 | ((uint64_t)r0 << 15) | ((uint64_t)rp1 << 30);
            bool keep = valid && ((nb & pm) == 0ull);

            uint32_t nw = __ballot_sync(0xFFFFFFFFu, keep);
            if (lane == 0) {
                uint32_t old = kept[KPAD + w];
                if (old != nw) {
                    kept[KPAD + w] = nw;
                    atomicOr(&dirty[cur ^ 1][1 + (w >> 5)], 1u << (w & 31));
                    s_changed = 1;
                }
            }
        }
        __syncthreads();                 // all updates + flags visible
        int done = !s_changed;
        __syncthreads();                 // all threads have read s_changed
        if (done) break;
        if (t < 18) dirty[cur][t] = 0;   // becomes write target next sweep
        if (t == 0) s_changed = 0;
        cur ^= 1;
        __syncthreads();
    }

    // Writeout: score if kept else 0.
    for (int w = wid; w < WORDS; w += 32) {
        int j = w * 32 + lane;
        if (j < NBOX) {
            bool k = (kept[KPAD + w] >> lane) & 1u;
            out[j * 5 + 4] = k ? __ldg(&x[j * 5 + 4]) : 0.0f;
        }
    }
}

// ---------------------------------------------------------------------------
extern "C" void kernel_launch(void* const* d_in, const int* in_sizes, int n_in,
                              void* d_out, int out_size)
{
    const float* x   = (const float*)d_in[0];
    float*       out = (float*)d_out;

    const int threads = 256;
    const int blocks  = (NBOX + threads - 1) / threads;   // 53

    decode_edges_kernel<<<blocks, threads>>>(x, out);
    nms_kernel<<<1, NMS_T>>>(x, out);
}

// round 3
// speedup vs baseline: 2.5304x; 2.3108x over previous
#include <cuda_runtime.h>
#include <cooperative_groups.h>
#include <stdint.h>

namespace cg = cooperative_groups;

#define GH 52
#define GW 52
#define NB 5
#define NBOX 13520                 // 52*52*5
#define WORDS 423                  // ceil(NBOX/32)
#define CTAS 8
#define OWN 53                     // words per CTA (last CTA owns 52)
#define HALO 9                     // 9*32=288 bits >= 260+ gather reach
#define LW 72                      // HALO + OWN + HALO + 1 straddle word
#define NMS_T 512
#define IOU_T 0.4f

// Per-box predecessor masks: x=row dy=-1, y=row dy=0, z=row dy=+1 (15 bits
// each, bit (dx+1)*5+bb), w unused (stays zero-init).
__device__ ushort4 g_pm[NBOX];

// ---------------------------------------------------------------------------
// Kernel 1: decode + per-row predecessor masks. One thread per (box, dy).
// Boxes are < 8px wide/tall, cell pitch 8px -> IoU>0 only within +/-1 cell.
// pred(i -> j) iff priority(i) > priority(j) (score desc, index asc) and
// IoU(i,j) > 0.4. Identical fp32 op sequence as the reference decode.
// ---------------------------------------------------------------------------
__global__ void decode_kernel(const float* __restrict__ x, float* __restrict__ out)
{
    int id = blockIdx.x * blockDim.x + threadIdx.x;
    if (id >= 3 * NBOX) return;
    int dyI = id / NBOX;           // 0,1,2 -> dy = dyI-1
    int j   = id - dyI * NBOX;

    int cell = j / NB;
    int b    = j - cell * NB;
    int gy   = cell / GW;
    int gx   = cell - gy * GW;

    const float sx = 416.0f / GW;  // 8
    const float sy = 416.0f / GH;  // 8

    const float* p = x + j * 5;
    float c0 = p[0], c1 = p[1], c2 = p[2], c3 = p[3], sj = p[4];

    float cx = (c0 + (float)gx) * sx;
    float w  = c2 * sx;
    float cy = (c1 + (float)gy) * sy;
    float h  = c3 * sy;
    cy = 416.0f - cy;
    float jx1 = cx - w * 0.5f, jy1 = cy - h * 0.5f;
    float jx2 = cx + w * 0.5f, jy2 = cy + h * 0.5f;

    if (dyI == 1) {
        float* o = out + j * 5;
        o[0] = jx1; o[1] = jy1; o[2] = jx2; o[3] = jy2;
        // o[4] written by nms_kernel.
    }

    float aj = fmaxf(jx2 - jx1, 0.0f) * fmaxf(jy2 - jy1, 0.0f);

    unsigned mask = 0;
    int ny = gy + dyI - 1;
    if ((unsigned)ny < GH) {
        #pragma unroll
        for (int dxi = 0; dxi < 3; dxi++) {
            int nx = gx + dxi - 1;
            if ((unsigned)nx >= GW) continue;
            int ncell = ny * GW + nx;
            #pragma unroll
            for (int bb = 0; bb < NB; bb++) {
                int i = ncell * NB + bb;
                if (i == j) continue;
                const float* q = x + i * 5;
                float si = q[4];
                bool higher = (si > sj) || (si == sj && i < j);
                if (!higher) continue;
                float d0 = q[0], d1 = q[1], d2 = q[2], d3 = q[3];
                float icx = (d0 + (float)nx) * sx;
                float iw_ = d2 * sx;
                float icy = (d1 + (float)ny) * sy;
                float ih_ = d3 * sy;
                icy = 416.0f - icy;
                float ix1 = icx - iw_ * 0.5f, iy1 = icy - ih_ * 0.5f;
                float ix2 = icx + iw_ * 0.5f, iy2 = icy + ih_ * 0.5f;

                float iw = fmaxf(fminf(ix2, jx2) - fmaxf(ix1, jx1), 0.0f);
                float ih = fmaxf(fminf(iy2, jy2) - fmaxf(iy1, jy1), 0.0f);
                float inter = iw * ih;
                float ai  = fmaxf(ix2 - ix1, 0.0f) * fmaxf(iy2 - iy1, 0.0f);
                float uni = ai + aj - inter;
                float iou = (uni > 0.0f) ? inter / fmaxf(uni, 1e-12f) : 0.0f;
                if (iou > IOU_T)
                    mask |= 1u << (dxi * 5 + bb);
            }
        }
    }
    ((unsigned short*)&g_pm[j])[dyI] = (unsigned short)mask;
}

// ---------------------------------------------------------------------------
// Kernel 2: clustered fixpoint NMS. 8 CTAs x 512 threads, one cluster.
// Each CTA owns 53 kept-words in local smem; halo read from neighbors via
// DSMEM each sweep (racy reads are safe: well-founded recursion -> chaotic
// async iteration converges to the unique fixpoint = exact greedy NMS).
// One cluster.sync per sweep; converged when no CTA changed any word.
// ---------------------------------------------------------------------------
__device__ __forceinline__ uint32_t gather15(const uint32_t* L, int bit)
{
    int wi = bit >> 5;
    return __funnelshift_r(L[wi], L[wi + 1], bit) & 0x7FFFu;
}

__global__ void __cluster_dims__(CTAS, 1, 1)
nms_kernel(const float* __restrict__ x, float* __restrict__ out)
{
    __shared__ uint32_t L[LW];
    __shared__ int sCh[3];
    __shared__ int sAny;

    cg::cluster_group cl = cg::this_cluster();
    int r    = cl.block_rank();
    int t    = threadIdx.x;
    int lane = t & 31;
    int wid  = t >> 5;

    int w0     = r * OWN;
    int ownCnt = min(WORDS - w0, OWN);

    // Init kept: valid boxes = 1; word WORDS-1 keeps only 16 valid bits;
    // out-of-range / padding words = 0.
    for (int i = t; i < LW; i += NMS_T) {
        int gw = w0 - HALO + i;
        uint32_t v = 0;
        if (gw >= 0 && gw < WORDS)
            v = (gw == WORDS - 1) ? 0x0000FFFFu : 0xFFFFFFFFu;
        L[i] = v;
    }
    if (t < 3) sCh[t] = 0;
    if (t == 0) sAny = 1;

    // Peer pointers.
    uint32_t* Lprev = (r > 0)        ? (uint32_t*)cl.map_shared_rank(L, r - 1) : 0;
    uint32_t* Lnext = (r < CTAS - 1) ? (uint32_t*)cl.map_shared_rank(L, r + 1) : 0;
    int* chp = (t < CTAS) ? (int*)cl.map_shared_rank(sCh, t) : 0;

    // Per-thread static assignment: up to 4 words per warp (k = wid + s*16).
    bool act[4]; bool val[4];
    int  lis[4]; int lbs[4];
    uint32_t pA[4], pB[4], pC[4];
    #pragma unroll
    for (int s = 0; s < 4; s++) {
        int k = wid + s * 16;
        bool a = k < ownCnt;
        act[s] = a;
        int kk = a ? k : 0;
        int j  = (w0 + kk) * 32 + lane;
        bool v = a && (j < NBOX);
        val[s] = v;
        ushort4 pm = v ? g_pm[j] : make_ushort4(0, 0, 0, 0);
        pA[s] = pm.x; pB[s] = pm.y; pC[s] = pm.z;
        int b = j % 5;
        lis[s] = HALO + kk;
        lbs[s] = (HALO + kk) * 32 + lane - b - 5;
    }

    cl.sync();   // init visible cluster-wide

    int slot = 0;
    for (int sweep = 0; sweep < NBOX; sweep++) {
        // Refresh halo from neighbors (racy vs their in-flight sweep: safe).
        if (t < HALO) {
            if (Lprev) L[t] = Lprev[t + OWN];
        } else if (t >= 32 && t < 32 + HALO + 1) {
            int li = (OWN + HALO) + (t - 32);           // 62..71
            if (Lnext) L[li] = Lnext[li - OWN];
        }
        // Reset next sweep's flag slot (safe: its last readers finished
        // before the previous cluster.sync).
        if (t == NMS_T - 1) sCh[slot == 2 ? 0 : slot + 1] = 0;
        __syncthreads();

        bool ch = false;
        #pragma unroll
        for (int s = 0; s < 4; s++) {
            if (!act[s]) continue;
            int lb = lbs[s];
            uint32_t rm1 = gather15(L, lb - 260);
            uint32_t r0  = gather15(L, lb);
            uint32_t rp1 = gather15(L, lb + 260);
            uint32_t sup = (rm1 & pA[s]) | (r0 & pB[s]) | (rp1 & pC[s]);
            bool keep = val[s] && (sup == 0u);
            uint32_t nw = __ballot_sync(0xFFFFFFFFu, keep);
            if (lane == 0 && L[lis[s]] != nw) { L[lis[s]] = nw; ch = true; }
        }
        if (ch) sCh[slot] = 1;          // benign race, all store 1
        cl.sync();                       // updates + flags visible

        // Gather change flags from all CTAs (slot stable until sweep+3).
        bool mine = (t < CTAS) ? (chp[slot] != 0) : false;
        uint32_t bal = __ballot_sync(0xFFFFFFFFu, mine);
        if (t == 0) sAny = (int)(bal & 0xFFu);
        __syncthreads();
        if (!sAny) break;
        slot = (slot == 2) ? 0 : slot + 1;
    }

    // Writeout: score if kept else 0, for own words.
    #pragma unroll
    for (int s = 0; s < 4; s++) {
        if (!act[s] || !val[s]) continue;
        int k = wid + s * 16;
        int j = (w0 + k) * 32 + lane;
        bool keep = (L[HALO + k] >> lane) & 1u;
        out[j * 5 + 4] = keep ? __ldg(&x[j * 5 + 4]) : 0.0f;
    }
}

// ---------------------------------------------------------------------------
extern "C" void kernel_launch(void* const* d_in, const int* in_sizes, int n_in,
                              void* d_out, int out_size)
{
    const float* x   = (const float*)d_in[0];
    float*       out = (float*)d_out;

    decode_kernel<<<(3 * NBOX + 255) / 256, 256>>>(x, out);
    nms_kernel<<<CTAS, NMS_T>>>(x, out);
}